// round 15
// baseline (speedup 1.0000x reference)
#include <cuda_runtime.h>
#include <math.h>

#define BB 2
#define NN 256
#define FF 64
#define HH 64
#define HEADS 4
#define CC 256
#define EPSV 1e-5f
#define INFV 1e5f

typedef unsigned long long u64;
typedef unsigned int u32;

// ---------------- scratch (device globals) ----------------------------------
__device__ float g_eT[BB*NN*HH*NN];         // [bi][h][j]
__device__ float g_sem[BB*NN*NN*HEADS];
__device__ float g_AT[BB*HH*NN];            // A[b][k][j] = h_j @ W1[0:64]
__device__ float g_acci[BB*NN*HH];          // acci[bi][k] = b1 + h_i @ W1[64:128]
__device__ float g_combnorm[BB*NN*CC];
__device__ float g_hagg[BB*NN*CC];
__device__ float g_deltav[BB*NN*3];

__device__ __forceinline__ float silu_f(float v){ return __fdividef(v, 1.f + __expf(-v)); }

__device__ __forceinline__ u64 pack2(float lo, float hi){
    u64 r; unsigned lu = __float_as_uint(lo), hu = __float_as_uint(hi);
    asm("mov.b64 %0, {%1, %2};" : "=l"(r) : "r"(lu), "r"(hu));
    return r;
}
__device__ __forceinline__ float2 unpack2(u64 v){
    unsigned lu, hu;
    asm("mov.b64 {%0, %1}, %2;" : "=r"(lu), "=r"(hu) : "l"(v));
    return make_float2(__uint_as_float(lu), __uint_as_float(hu));
}
#define FMA2(acc,a,b) asm("fma.rn.f32x2 %0, %1, %2, %3;" : "=l"(acc) : "l"(a), "l"(b), "l"(acc))

__device__ __forceinline__ u32 smem_u32(const void* p){
    u32 a;
    asm("{ .reg .u64 tmp; cvta.to.shared.u64 tmp, %1; cvt.u32.u64 %0, tmp; }"
        : "=r"(a) : "l"(p));
    return a;
}
__device__ __forceinline__ void cpa16(u32 dst, const void* src){
    asm volatile("cp.async.cg.shared.global [%0], [%1], 16;" :: "r"(dst), "l"(src));
}
#define CPA_COMMIT()  asm volatile("cp.async.commit_group;" ::: "memory")
#define CPA_WAIT(N)   asm volatile("cp.async.wait_group %0;" :: "n"(N) : "memory")

extern __shared__ float sm[];

__device__ __forceinline__ float warpmaxf(float v){
    #pragma unroll
    for (int s=16;s;s>>=1) v = fmaxf(v, __shfl_xor_sync(0xffffffffu, v, s));
    return v;
}
__device__ __forceinline__ float warpsumf(float v){
    #pragma unroll
    for (int s=16;s;s>>=1) v += __shfl_xor_sync(0xffffffffu, v, s);
    return v;
}

// ---------------- kernel P: precompute A and acci (smem-staged W1) ----------
__global__ __launch_bounds__(256) void pre_kernel(
        const float* __restrict__ h, const float* __restrict__ w1,
        const float* __restrict__ b1)
{
    __shared__ float w1s[128*64];   // 32KB
    __shared__ float hs[2][64];
    __shared__ float b1s[64];
    int t = threadIdx.x;
    int blk = blockIdx.x;
    u32 smb = smem_u32(w1s);
    #pragma unroll
    for (int q = 0; q < 8; q++)
        cpa16(smb + t*16 + q*4096, (const char*)w1 + t*16 + q*4096);
    CPA_COMMIT();
    if (t < 128) hs[t>>6][t&63] = h[blk*2*FF + t];
    if (t < 64)  b1s[t] = b1[t];
    CPA_WAIT(0);
    __syncthreads();

    int k = t & 63, r = t >> 6;
    int jj = r >> 1, part = r & 1;
    const float* wb = &w1s[part*64*64];
    const float* hv = hs[jj];
    float a0=0,a1=0,a2=0,a3=0;
    #pragma unroll 8
    for (int f = 0; f < 64; f += 4) {
        a0 += hv[f+0]*wb[(f+0)*64 + k];
        a1 += hv[f+1]*wb[(f+1)*64 + k];
        a2 += hv[f+2]*wb[(f+2)*64 + k];
        a3 += hv[f+3]*wb[(f+3)*64 + k];
    }
    float a = (a0+a1)+(a2+a3);
    int bi = blk*2 + jj, b = bi >> 8, j = bi & 255;
    if (part == 0) g_AT[(b*HH + k)*NN + j] = a;
    else           g_acci[bi*HH + k] = a + b1s[k];
}

// ---------------- kernel A: edge layer2 + sem, smem-dup weights -------------
// grid: BB*NN*2 = 1024 (bi, half of 128 j), block 256, dynamic smem.
#define E_W2D   0        // u64[4096] = 8192 floats (16B aligned at 0)
#define E_HID   8192     // 64*132
#define E_ACCI  16640    // 64
#define E_W1X   16704    // 64
#define E_XN    16768    // 128
#define E_SSW   16896    // 256
#define E_SSB   17152    // 4
#define EDGE_SMEM_FLOATS 17160

__global__ __launch_bounds__(256) void edge_kernel(
        const float* __restrict__ x,
        const float* __restrict__ w1,
        const float* __restrict__ w2, const float* __restrict__ b2,
        const float* __restrict__ sw, const float* __restrict__ sb)
{
    int blk = blockIdx.x;
    int bi = blk >> 1, half = blk & 1;
    int b = bi >> 8, i = bi & 255;
    int t = threadIdx.x;
    int tx = t & 15, ty = t >> 4;          // k = tx*4, j = ty*8

    float* hid = &sm[E_HID];
    u64* w2d = (u64*)&sm[E_W2D];

    // build duplicated-weight table (16 independent LDG each)
    #pragma unroll
    for (int q = 0; q < 16; q++) {
        int idx = t + q*256;
        float w = __ldg(&w2[idx]);
        w2d[idx] = pack2(w, w);
    }
    if (t < 64) { sm[E_ACCI+t] = g_acci[bi*HH + t]; sm[E_W1X+t] = w1[128*HH + t]; }
    sm[E_SSW+t] = sw[t];
    if (t < 4) sm[E_SSB+t] = sb[t];
    if (t < 128) {
        int j = half*128 + t;
        float dx = x[(b*NN + j)*3+0] - x[(b*NN + i)*3+0];
        float dy = x[(b*NN + j)*3+1] - x[(b*NN + i)*3+1];
        float dz = x[(b*NN + j)*3+2] - x[(b*NN + i)*3+2];
        sm[E_XN+t] = sqrtf(dx*dx + dy*dy + dz*dz + EPSV);
    }
    __syncthreads();

    // ---- layer-1 elementwise for all 128 j of this half ----
    {
        int k = t >> 2, jg = t & 3;
        float ac = sm[E_ACCI+k], wx = sm[E_W1X+k];
        const float* Arow = &g_AT[(b*HH + k)*NN + half*128];
        #pragma unroll
        for (int q = 0; q < 8; q++) {
            int jl = jg*32 + q*4;
            float4 av = *(const float4*)&Arow[jl];
            float4 xv = *(const float4*)&sm[E_XN + jl];
            float4 hv;
            hv.x = silu_f(fmaf(xv.x, wx, av.x + ac));
            hv.y = silu_f(fmaf(xv.y, wx, av.y + ac));
            hv.z = silu_f(fmaf(xv.z, wx, av.z + ac));
            hv.w = silu_f(fmaf(xv.w, wx, av.w + ac));
            *(float4*)&hid[k*132 + jl] = hv;
        }
    }
    __syncthreads();

    // ---- layer 2: 8j x 4k per thread, j-pairs packed, weights pre-dup ------
    float eb[8][4];
    {
        u64 acc[4][4];
        float4 bv = *(const float4*)&b2[tx*4];
        u64 bd0 = pack2(bv.x, bv.x), bd1 = pack2(bv.y, bv.y);
        u64 bd2 = pack2(bv.z, bv.z), bd3 = pack2(bv.w, bv.w);
        #pragma unroll
        for (int jp = 0; jp < 4; jp++) {
            acc[jp][0] = bd0; acc[jp][1] = bd1; acc[jp][2] = bd2; acc[jp][3] = bd3;
        }
        #pragma unroll 4
        for (int kf = 0; kf < 64; kf++) {
            const u64* wrow = &w2d[kf*64 + tx*4];
            ulonglong2 wa = *(const ulonglong2*)wrow;
            ulonglong2 wbp = *(const ulonglong2*)(wrow+2);
            u64 wd0 = wa.x, wd1 = wa.y, wd2 = wbp.x, wd3 = wbp.y;
            float4 a0 = *(float4*)&hid[kf*132 + ty*8];
            float4 a1 = *(float4*)&hid[kf*132 + ty*8 + 4];
            u64 ap0 = pack2(a0.x, a0.y), ap1 = pack2(a0.z, a0.w);
            u64 ap2 = pack2(a1.x, a1.y), ap3 = pack2(a1.z, a1.w);
            FMA2(acc[0][0],ap0,wd0); FMA2(acc[0][1],ap0,wd1); FMA2(acc[0][2],ap0,wd2); FMA2(acc[0][3],ap0,wd3);
            FMA2(acc[1][0],ap1,wd0); FMA2(acc[1][1],ap1,wd1); FMA2(acc[1][2],ap1,wd2); FMA2(acc[1][3],ap1,wd3);
            FMA2(acc[2][0],ap2,wd0); FMA2(acc[2][1],ap2,wd1); FMA2(acc[2][2],ap2,wd2); FMA2(acc[2][3],ap2,wd3);
            FMA2(acc[3][0],ap3,wd0); FMA2(acc[3][1],ap3,wd1); FMA2(acc[3][2],ap3,wd2); FMA2(acc[3][3],ap3,wd3);
        }
        #pragma unroll
        for (int jp = 0; jp < 4; jp++) {
            #pragma unroll
            for (int kk = 0; kk < 4; kk++) {
                float2 p = unpack2(acc[jp][kk]);
                eb[jp*2+0][kk] = silu_f(p.x);
                eb[jp*2+1][kk] = silu_f(p.y);
            }
        }
    }
    // store e to g_eT[bi][h][j]
    #pragma unroll
    for (int kk = 0; kk < 4; kk++) {
        float4 e0 = make_float4(eb[0][kk], eb[1][kk], eb[2][kk], eb[3][kk]);
        float4 e1 = make_float4(eb[4][kk], eb[5][kk], eb[6][kk], eb[7][kk]);
        float* dst = &g_eT[(bi*HH + tx*4+kk)*NN + half*128 + ty*8];
        *(float4*)dst = e0;
        *(float4*)(dst+4) = e1;
    }
    __syncthreads();   // all GEMM reads of hid done

    // ---- sem logits: partials over k (split by tx) into hid region ----
    {
        float* sempart = hid;       // 16*128*4 = 8192 floats <= 64*132
        #pragma unroll
        for (int jj = 0; jj < 8; jj++) {
            float p0=0.f, p1=0.f, p2=0.f, p3=0.f;
            #pragma unroll
            for (int kk = 0; kk < 4; kk++) {
                float e = eb[jj][kk];
                const float* swr = &sm[E_SSW + (tx*4+kk)*4];
                p0 += e*swr[0]; p1 += e*swr[1]; p2 += e*swr[2]; p3 += e*swr[3];
            }
            float* dst = &sempart[(tx*128 + ty*8+jj)*4];
            dst[0]=p0; dst[1]=p1; dst[2]=p2; dst[3]=p3;
        }
        __syncthreads();
        int jl = t >> 1, hdp = (t & 1)*2;
        #pragma unroll
        for (int hq = 0; hq < 2; hq++) {
            int hd = hdp + hq;
            float a = sm[E_SSB+hd];
            #pragma unroll
            for (int r = 0; r < 16; r++) a += sempart[(r*128 + jl)*4 + hd];
            a = (a > 0.f) ? a : 0.2f*a;
            g_sem[(bi*NN + half*128 + jl)*HEADS + hd] = a;
        }
    }
}

// ---------------- kernel B: attention + aggregation, 512 thr, fused reds ----
#define A_ET    0        // 64*260
#define A_SATT  16640    // 4*260
#define A_UT    17680    // 3*260
#define A_RED   18460    // 16*8
#define A_PART  18588    // 256*4
#define A_WPART 19612    // 8*3
#define ATT_SMEM_FLOATS 19640

__global__ __launch_bounds__(512) void attagg_kernel(
        const float* __restrict__ x, const float* __restrict__ vmix,
        const float* __restrict__ log_gamma)
{
    int bi = blockIdx.x;
    int b = bi >> 8, i = bi & 255;
    int t = threadIdx.x;

    // load full eT tile (64 x 256) — latency hidden behind softmax chain
    {
        const float* src = &g_eT[bi*HH*NN];
        #pragma unroll
        for (int q = 0; q < 8; q++) {
            int idx = t + q*512;
            int hr = idx >> 6, c4 = idx & 63;
            *(float4*)&sm[A_ET + hr*260 + c4*4] = *(const float4*)&src[hr*NN + c4*4];
        }
    }

    // ---- softmax (t < 256 holds j = t); interleaved euclid/sem reductions ----
    float v8[8];
    float diag = 0.f, xn = 0.f;
    if (t < 256) {
        float4 lg = *(const float4*)log_gamma;
        float4 gm = make_float4(__expf(lg.x), __expf(lg.y), __expf(lg.z), __expf(lg.w));
        float dx = x[(b*NN+t)*3+0] - x[(b*NN+i)*3+0];
        float dy = x[(b*NN+t)*3+1] - x[(b*NN+i)*3+1];
        float dz = x[(b*NN+t)*3+2] - x[(b*NN+i)*3+2];
        xn = sqrtf(dx*dx + dy*dy + dz*dz + EPSV);
        float inv = __fdividef(1.f, xn + EPSV);
        sm[A_UT + 0*260 + t] = dx * inv;
        sm[A_UT + 1*260 + t] = dy * inv;
        sm[A_UT + 2*260 + t] = dz * inv;
        diag = (t == i) ? INFV : 0.f;
        float xm = xn + diag;
        v8[0] = -xm*gm.x; v8[1] = -xm*gm.y; v8[2] = -xm*gm.z; v8[3] = -xm*gm.w;
        v8[4] = sm ? 0.f : 0.f;  // placeholder (overwritten below)
        const float4 sl = *(const float4*)&g_sem[(bi*NN + t)*HEADS];
        v8[4] = sl.x - diag; v8[5] = sl.y - diag; v8[6] = sl.z - diag; v8[7] = sl.w - diag;
    }
    float l1s[8];
    #pragma unroll
    for (int q = 0; q < 8; q++) l1s[q] = v8[q];

    // reduction 1: max over j of all 8 logits
    if (t < 256) {
        #pragma unroll
        for (int q = 0; q < 8; q++) v8[q] = warpmaxf(v8[q]);
        if ((t & 31) == 0) {
            #pragma unroll
            for (int q = 0; q < 8; q++) sm[A_RED + (t>>5)*8 + q] = v8[q];
        }
    }
    __syncthreads();
    float mx[8];
    if (t < 256) {
        #pragma unroll
        for (int q = 0; q < 8; q++) {
            float m = sm[A_RED + q];
            #pragma unroll
            for (int w = 1; w < 8; w++) m = fmaxf(m, sm[A_RED + w*8 + q]);
            mx[q] = m;
        }
        #pragma unroll
        for (int q = 0; q < 8; q++) v8[q] = __expf(l1s[q] - mx[q]);
    }
    __syncthreads();
    // reduction 2: sums of all 8 exps
    float ex[8];
    if (t < 256) {
        #pragma unroll
        for (int q = 0; q < 8; q++) { ex[q] = v8[q]; v8[q] = warpsumf(v8[q]); }
        if ((t & 31) == 0) {
            #pragma unroll
            for (int q = 0; q < 8; q++) sm[A_RED + (t>>5)*8 + q] = v8[q];
        }
    }
    __syncthreads();
    float4 p4;
    if (t < 256) {
        #pragma unroll
        for (int q = 0; q < 8; q++) {
            float s = sm[A_RED + q];
            #pragma unroll
            for (int w = 1; w < 8; w++) s += sm[A_RED + w*8 + q];
            mx[q] = s;   // reuse as sums
        }
        p4.x = __fdividef(ex[0], mx[0]) * __fdividef(ex[4], mx[4]);
        p4.y = __fdividef(ex[1], mx[1]) * __fdividef(ex[5], mx[5]);
        p4.z = __fdividef(ex[2], mx[2]) * __fdividef(ex[6], mx[6]);
        p4.w = __fdividef(ex[3], mx[3]) * __fdividef(ex[7], mx[7]);
        v8[0]=p4.x; v8[1]=p4.y; v8[2]=p4.z; v8[3]=p4.w;
    }
    __syncthreads();
    // reduction 3: max of combined product (4)
    if (t < 256) {
        #pragma unroll
        for (int q = 0; q < 4; q++) v8[q] = warpmaxf(v8[q]);
        if ((t & 31) == 0) {
            #pragma unroll
            for (int q = 0; q < 4; q++) sm[A_RED + (t>>5)*8 + q] = v8[q];
        }
    }
    __syncthreads();
    float4 e4v;
    if (t < 256) {
        #pragma unroll
        for (int q = 0; q < 4; q++) {
            float m = sm[A_RED + q];
            #pragma unroll
            for (int w = 1; w < 8; w++) m = fmaxf(m, sm[A_RED + w*8 + q]);
            mx[q] = m;
        }
        e4v.x = __expf(p4.x - mx[0]); e4v.y = __expf(p4.y - mx[1]);
        e4v.z = __expf(p4.z - mx[2]); e4v.w = __expf(p4.w - mx[3]);
        v8[0]=e4v.x; v8[1]=e4v.y; v8[2]=e4v.z; v8[3]=e4v.w;
    }
    __syncthreads();
    // reduction 4: sum of final exps (4)
    if (t < 256) {
        #pragma unroll
        for (int q = 0; q < 4; q++) v8[q] = warpsumf(v8[q]);
        if ((t & 31) == 0) {
            #pragma unroll
            for (int q = 0; q < 4; q++) sm[A_RED + (t>>5)*8 + q] = v8[q];
        }
    }
    __syncthreads();
    if (t < 256) {
        #pragma unroll
        for (int q = 0; q < 4; q++) {
            float s = sm[A_RED + q];
            #pragma unroll
            for (int w = 1; w < 8; w++) s += sm[A_RED + w*8 + q];
            mx[q] = s;
        }
        sm[A_SATT + 0*260 + t] = __fdividef(e4v.x, mx[0]);
        sm[A_SATT + 1*260 + t] = __fdividef(e4v.y, mx[1]);
        sm[A_SATT + 2*260 + t] = __fdividef(e4v.z, mx[2]);
        sm[A_SATT + 3*260 + t] = __fdividef(e4v.w, mx[3]);
    }
    __syncthreads();

    // ---- aggregation: 512 threads = (c, j-half) ----
    {
        int c = t & 255, hf = t >> 8;
        int hh = c >> 2, hd = c & 3;
        float agg = 0.f, cs0 = 0.f, cs1 = 0.f, cs2 = 0.f;
        const float* erow = &sm[A_ET + hh*260 + hf*128];
        const float* arow = &sm[A_SATT + hd*260 + hf*128];
        const float* u0r = &sm[A_UT + 0*260 + hf*128];
        const float* u1r = &sm[A_UT + 1*260 + hf*128];
        const float* u2r = &sm[A_UT + 2*260 + hf*128];
        #pragma unroll 4
        for (int q = 0; q < 32; q++) {
            float4 e4 = *(const float4*)&erow[q*4];
            float4 a4 = *(const float4*)&arow[q*4];
            float4 u0 = *(const float4*)&u0r[q*4];
            float4 u1 = *(const float4*)&u1r[q*4];
            float4 u2 = *(const float4*)&u2r[q*4];
            float w0 = e4.x*a4.x, w1 = e4.y*a4.y, w2 = e4.z*a4.z, w3 = e4.w*a4.w;
            agg += (w0 + w1) + (w2 + w3);
            cs0 += w0*u0.x + w1*u0.y + w2*u0.z + w3*u0.w;
            cs1 += w0*u1.x + w1*u1.y + w2*u1.z + w3*u1.w;
            cs2 += w0*u2.x + w1*u2.y + w2*u2.z + w3*u2.w;
        }
        if (hf == 1) {
            float* p = &sm[A_PART + c*4];
            p[0]=agg; p[1]=cs0; p[2]=cs1; p[3]=cs2;
        }
        __syncthreads();
        if (hf == 0) {
            const float* p = &sm[A_PART + c*4];
            agg += p[0]; cs0 += p[1]; cs1 += p[2]; cs2 += p[3];
            const float inv_n = 1.f / (float)NN;
            cs0 *= inv_n; cs1 *= inv_n; cs2 *= inv_n;
            g_hagg[bi*CC + c]     = agg;
            g_combnorm[bi*CC + c] = cs0*cs0 + cs1*cs1 + cs2*cs2;
            float vm = vmix[c];
            float d0 = warpsumf(vm*cs0);
            float d1 = warpsumf(vm*cs1);
            float d2 = warpsumf(vm*cs2);
            if ((t & 31) == 0) {
                float* wp = &sm[A_WPART + (t>>5)*3];
                wp[0]=d0; wp[1]=d1; wp[2]=d2;
            }
        }
        __syncthreads();
        if (t < 3) {
            float s = 0.f;
            #pragma unroll
            for (int w = 0; w < 8; w++) s += sm[A_WPART + w*3 + t];
            g_deltav[bi*3 + t] = s;
        }
    }
}

// ---------------- kernel C: node MLPs — cp.async pipelined (R9 version) -----
#define O_PW1  0        // 16384
#define O_PW2  16384    // 4096
#define O_NW1  20480    // 24576
#define O_NW2  45056    // 4096
#define O_PB1  49152
#define O_PB2  49216
#define O_NB1  49280
#define O_NB2  49344
#define O_CNT  49408    // 1024
#define O_NACT 50432    // 1536
#define O_HID  51968    // 256
#define O_HNEW 52224    // 256
#define O_SBUF 52480    // 2048
#define O_MISC 54528    // 16
#define NODE_SMEM_FLOATS 54544

__global__ __launch_bounds__(512) void node_kernel(
        const float* __restrict__ h, const float* __restrict__ x,
        const float* __restrict__ v,
        const float* __restrict__ pw1, const float* __restrict__ pb1,
        const float* __restrict__ pw2, const float* __restrict__ pb2,
        const float* __restrict__ nw1, const float* __restrict__ nb1,
        const float* __restrict__ nw2, const float* __restrict__ nb2,
        const float* __restrict__ vw1, const float* __restrict__ vb1,
        const float* __restrict__ vw2,
        float* __restrict__ out)
{
    int bi = blockIdx.x;
    int t = threadIdx.x;
    int k = t & 63, r = t >> 6;
    u32 smb = smem_u32(sm);

    for (int idx = t*16; idx < 65536; idx += 512*16)
        cpa16(smb + O_PW1*4 + idx, (const char*)pw1 + idx);
    if (t < 16) cpa16(smb + O_PB1*4 + t*16, (const char*)pb1 + t*16);
    CPA_COMMIT();
    for (int idx = t*16; idx < 16384; idx += 512*16)
        cpa16(smb + O_PW2*4 + idx, (const char*)pw2 + idx);
    if (t < 16) cpa16(smb + O_PB2*4 + t*16, (const char*)pb2 + t*16);
    CPA_COMMIT();
    for (int idx = t*16; idx < 98304; idx += 512*16)
        cpa16(smb + O_NW1*4 + idx, (const char*)nw1 + idx);
    if (t < 16) cpa16(smb + O_NB1*4 + t*16, (const char*)nb1 + t*16);
    CPA_COMMIT();
    for (int idx = t*16; idx < 16384; idx += 512*16)
        cpa16(smb + O_NW2*4 + idx, (const char*)nw2 + idx);
    if (t < 16) cpa16(smb + O_NB2*4 + t*16, (const char*)nb2 + t*16);
    CPA_COMMIT();

    if (t < 256) {
        int kk = t & 63, node = t >> 6;
        #pragma unroll
        for (int q = 0; q < 4; q++) {
            int u = kk + q*64;
            sm[O_CNT  + u*4 + node]      = g_combnorm[(bi*4 + node)*CC + u];
            sm[O_NACT + (64+u)*4 + node] = g_hagg[(bi*4 + node)*CC + u];
        }
        sm[O_NACT + kk*4 + node] = h[(bi*4 + node)*FF + kk];
    }

    CPA_WAIT(3);
    __syncthreads();

    // post1
    {
        float a0=0,a1=0,a2=0,a3=0;
        #pragma unroll 8
        for (int uu = 0; uu < 32; uu++) {
            int u = r*32 + uu;
            float w = sm[O_PW1 + u*HH + k];
            float4 a4 = *(float4*)&sm[O_CNT + u*4];
            a0 += a4.x*w; a1 += a4.y*w; a2 += a4.z*w; a3 += a4.w*w;
        }
        sm[O_SBUF+(r*4+0)*64+k]=a0; sm[O_SBUF+(r*4+1)*64+k]=a1;
        sm[O_SBUF+(r*4+2)*64+k]=a2; sm[O_SBUF+(r*4+3)*64+k]=a3;
    }
    CPA_WAIT(2);
    __syncthreads();
    if (t < 256) {
        int kk = t & 63, node = t >> 6;
        float s = sm[O_PB1+kk];
        #pragma unroll
        for (int q = 0; q < 8; q++) s += sm[O_SBUF+(q*4+node)*64+kk];
        sm[O_HID + kk*4+node] = silu_f(s);
    }
    __syncthreads();

    // post2
    {
        float a0=0,a1=0,a2=0,a3=0;
        #pragma unroll
        for (int uu = 0; uu < 8; uu++) {
            int u = r*8 + uu;
            float w = sm[O_PW2 + u*HH + k];
            float4 a4 = *(float4*)&sm[O_HID + u*4];
            a0 += a4.x*w; a1 += a4.y*w; a2 += a4.z*w; a3 += a4.w*w;
        }
        sm[O_SBUF+(r*4+0)*64+k]=a0; sm[O_SBUF+(r*4+1)*64+k]=a1;
        sm[O_SBUF+(r*4+2)*64+k]=a2; sm[O_SBUF+(r*4+3)*64+k]=a3;
    }
    CPA_WAIT(1);
    __syncthreads();
    if (t < 256) {
        int kk = t & 63, node = t >> 6;
        float s = sm[O_PB2+kk];
        #pragma unroll
        for (int q = 0; q < 8; q++) s += sm[O_SBUF+(q*4+node)*64+kk];
        sm[O_NACT + (320+kk)*4+node] = silu_f(s);
    }
    __syncthreads();

    // node1
    {
        float a0=0,a1=0,a2=0,a3=0;
        #pragma unroll 8
        for (int uu = 0; uu < 48; uu++) {
            int u = r*48 + uu;
            float w = sm[O_NW1 + u*HH + k];
            float4 a4 = *(float4*)&sm[O_NACT + u*4];
            a0 += a4.x*w; a1 += a4.y*w; a2 += a4.z*w; a3 += a4.w*w;
        }
        sm[O_SBUF+(r*4+0)*64+k]=a0; sm[O_SBUF+(r*4+1)*64+k]=a1;
        sm[O_SBUF+(r*4+2)*64+k]=a2; sm[O_SBUF+(r*4+3)*64+k]=a3;
    }
    CPA_WAIT(0);
    __syncthreads();
    if (t < 256) {
        int kk = t & 63, node = t >> 6;
        float s = sm[O_NB1+kk];
        #pragma unroll
        for (int q = 0; q < 8; q++) s += sm[O_SBUF+(q*4+node)*64+kk];
        sm[O_HID + kk*4+node] = silu_f(s);
    }
    __syncthreads();

    // node2 + residual
    {
        float a0=0,a1=0,a2=0,a3=0;
        #pragma unroll
        for (int uu = 0; uu < 8; uu++) {
            int u = r*8 + uu;
            float w = sm[O_NW2 + u*HH + k];
            float4 a4 = *(float4*)&sm[O_HID + u*4];
            a0 += a4.x*w; a1 += a4.y*w; a2 += a4.z*w; a3 += a4.w*w;
        }
        sm[O_SBUF+(r*4+0)*64+k]=a0; sm[O_SBUF+(r*4+1)*64+k]=a1;
        sm[O_SBUF+(r*4+2)*64+k]=a2; sm[O_SBUF+(r*4+3)*64+k]=a3;
    }
    __syncthreads();
    if (t < 256) {
        int kk = t & 63, node = t >> 6;
        float s = sm[O_NB2+kk];
        #pragma unroll
        for (int q = 0; q < 8; q++) s += sm[O_SBUF+(q*4+node)*64+kk];
        float hn = sm[O_NACT + kk*4+node] + silu_f(s);
        sm[O_HNEW + kk*4+node] = hn;
        out[(bi*4+node)*FF + kk] = hn;
    }
    __syncthreads();

    // vel
    {
        float a0=0,a1=0,a2=0,a3=0;
        #pragma unroll
        for (int uu = 0; uu < 8; uu++) {
            int u = r*8 + uu;
            float w = __ldg(&vw1[u*HH + k]);
            float4 a4 = *(float4*)&sm[O_HNEW + u*4];
            a0 += a4.x*w; a1 += a4.y*w; a2 += a4.z*w; a3 += a4.w*w;
        }
        sm[O_SBUF+(r*4+0)*64+k]=a0; sm[O_SBUF+(r*4+1)*64+k]=a1;
        sm[O_SBUF+(r*4+2)*64+k]=a2; sm[O_SBUF+(r*4+3)*64+k]=a3;
    }
    __syncthreads();
    if (t < 256) {
        int kk = t & 63, node = t >> 6;
        float s = 0.f;
        #pragma unroll
        for (int q = 0; q < 8; q++) s += sm[O_SBUF+(q*4+node)*64+kk];
        float sv = silu_f(s + __ldg(&vb1[kk])) * __ldg(&vw2[kk]);
        sv = warpsumf(sv);
        if ((t & 31) == 0) sm[O_MISC + 4 + (t >> 5)] = sv;
    }
    __syncthreads();
    if (t < 4) sm[O_MISC + t] = sm[O_MISC+4 + t*2] + sm[O_MISC+4 + t*2+1];
    __syncthreads();
    if (t < 12) {
        int nd = t / 3, d = t % 3;
        int gi = bi*4 + nd;
        float vv = v[gi*3 + d];
        float vn = g_deltav[gi*3 + d] + sm[O_MISC + nd]*vv;
        out[BB*NN*FF + gi*3 + d]            = x[gi*3 + d] + vn;
        out[BB*NN*FF + BB*NN*3 + gi*3 + d]  = vn;
    }
}

// ---------------------------------------------------------------------------
extern "C" void kernel_launch(void* const* d_in, const int* in_sizes, int n_in,
                              void* d_out, int out_size)
{
    const float* h        = (const float*)d_in[0];
    const float* x        = (const float*)d_in[1];
    const float* v        = (const float*)d_in[2];
    const float* edge_w1  = (const float*)d_in[3];
    const float* edge_b1  = (const float*)d_in[4];
    const float* edge_w2  = (const float*)d_in[5];
    const float* edge_b2  = (const float*)d_in[6];
    const float* sem_w    = (const float*)d_in[7];
    const float* sem_b    = (const float*)d_in[8];
    const float* post_w1  = (const float*)d_in[9];
    const float* post_b1  = (const float*)d_in[10];
    const float* post_w2  = (const float*)d_in[11];
    const float* post_b2  = (const float*)d_in[12];
    const float* node_w1  = (const float*)d_in[13];
    const float* node_b1  = (const float*)d_in[14];
    const float* node_w2  = (const float*)d_in[15];
    const float* node_b2  = (const float*)d_in[16];
    const float* vel_w1   = (const float*)d_in[17];
    const float* vel_b1   = (const float*)d_in[18];
    const float* vel_w2   = (const float*)d_in[19];
    const float* vmix_w   = (const float*)d_in[20];
    const float* log_gamma= (const float*)d_in[21];
    float* out = (float*)d_out;

    static int cfg_done = 0;
    if (!cfg_done) {
        cudaFuncSetAttribute(node_kernel,
                             cudaFuncAttributeMaxDynamicSharedMemorySize,
                             NODE_SMEM_FLOATS * (int)sizeof(float));
        cudaFuncSetAttribute(edge_kernel,
                             cudaFuncAttributeMaxDynamicSharedMemorySize,
                             EDGE_SMEM_FLOATS * (int)sizeof(float));
        cudaFuncSetAttribute(attagg_kernel,
                             cudaFuncAttributeMaxDynamicSharedMemorySize,
                             ATT_SMEM_FLOATS * (int)sizeof(float));
        cfg_done = 1;
    }

    pre_kernel<<<BB*NN/2, 256>>>(h, edge_w1, edge_b1);
    edge_kernel<<<BB*NN*2, 256, EDGE_SMEM_FLOATS * sizeof(float)>>>(
                                  x, edge_w1, edge_w2, edge_b2, sem_w, sem_b);
    attagg_kernel<<<BB*NN, 512, ATT_SMEM_FLOATS * sizeof(float)>>>(
                                  x, vmix_w, log_gamma);
    node_kernel<<<BB*NN/4, 512, NODE_SMEM_FLOATS * sizeof(float)>>>(
                                  h, x, v,
                                  post_w1, post_b1, post_w2, post_b2,
                                  node_w1, node_b1, node_w2, node_b2,
                                  vel_w1, vel_b1, vel_w2, out);
}

// round 16
// speedup vs baseline: 1.2114x; 1.2114x over previous
#include <cuda_runtime.h>
#include <math.h>

#define BB 2
#define NN 256
#define FF 64
#define HH 64
#define HEADS 4
#define CC 256
#define EPSV 1e-5f
#define INFV 1e5f

typedef unsigned long long u64;
typedef unsigned int u32;

// ---------------- scratch (device globals) ----------------------------------
__device__ float g_eT[BB*NN*HH*NN];         // [bi][h][j]
__device__ float g_sem[BB*NN*NN*HEADS];
__device__ float g_AT[BB*HH*NN];            // A[b][k][j] = h_j @ W1[0:64]
__device__ float g_acci[BB*NN*HH];          // acci[bi][k] = b1 + h_i @ W1[64:128]
__device__ float g_combnorm[BB*NN*CC];
__device__ float g_hagg[BB*NN*CC];
__device__ float g_deltav[BB*NN*3];

__device__ __forceinline__ float silu_f(float v){ return __fdividef(v, 1.f + __expf(-v)); }

__device__ __forceinline__ u64 pack2(float lo, float hi){
    u64 r; unsigned lu = __float_as_uint(lo), hu = __float_as_uint(hi);
    asm("mov.b64 %0, {%1, %2};" : "=l"(r) : "r"(lu), "r"(hu));
    return r;
}
__device__ __forceinline__ float2 unpack2(u64 v){
    unsigned lu, hu;
    asm("mov.b64 {%0, %1}, %2;" : "=r"(lu), "=r"(hu) : "l"(v));
    return make_float2(__uint_as_float(lu), __uint_as_float(hu));
}
#define FMA2(acc,a,b) asm("fma.rn.f32x2 %0, %1, %2, %3;" : "=l"(acc) : "l"(a), "l"(b), "l"(acc))

__device__ __forceinline__ u32 smem_u32(const void* p){
    u32 a;
    asm("{ .reg .u64 tmp; cvta.to.shared.u64 tmp, %1; cvt.u32.u64 %0, tmp; }"
        : "=r"(a) : "l"(p));
    return a;
}
__device__ __forceinline__ void cpa16(u32 dst, const void* src){
    asm volatile("cp.async.cg.shared.global [%0], [%1], 16;" :: "r"(dst), "l"(src));
}
#define CPA_COMMIT()  asm volatile("cp.async.commit_group;" ::: "memory")
#define CPA_WAIT(N)   asm volatile("cp.async.wait_group %0;" :: "n"(N) : "memory")

extern __shared__ float sm[];

__device__ __forceinline__ float warpmaxf(float v){
    #pragma unroll
    for (int s=16;s;s>>=1) v = fmaxf(v, __shfl_xor_sync(0xffffffffu, v, s));
    return v;
}
__device__ __forceinline__ float warpsumf(float v){
    #pragma unroll
    for (int s=16;s;s>>=1) v += __shfl_xor_sync(0xffffffffu, v, s);
    return v;
}
__device__ __forceinline__ float4 blk_reduce4(float4 v, bool is_max, float4* redbuf){
    if (is_max) { v.x=warpmaxf(v.x); v.y=warpmaxf(v.y); v.z=warpmaxf(v.z); v.w=warpmaxf(v.w); }
    else        { v.x=warpsumf(v.x); v.y=warpsumf(v.y); v.z=warpsumf(v.z); v.w=warpsumf(v.w); }
    int w = threadIdx.x>>5, l = threadIdx.x&31;
    if (l == 0) redbuf[w] = v;
    __syncthreads();
    float4 r = redbuf[0];
    #pragma unroll
    for (int q = 1; q < 8; q++) {
        float4 o = redbuf[q];
        if (is_max) { r.x=fmaxf(r.x,o.x); r.y=fmaxf(r.y,o.y); r.z=fmaxf(r.z,o.z); r.w=fmaxf(r.w,o.w); }
        else        { r.x+=o.x; r.y+=o.y; r.z+=o.z; r.w+=o.w; }
    }
    __syncthreads();
    return r;
}
__device__ __forceinline__ float blk_sum256(float v, float* red) {
    int t = threadIdx.x;
    red[t] = v; __syncthreads();
    for (int s = 128; s > 0; s >>= 1) {
        if (t < s) red[t] += red[t + s];
        __syncthreads();
    }
    float r = red[0]; __syncthreads();
    return r;
}

// ---------------- kernel P: precompute A and acci (smem-staged W1) ----------
__global__ __launch_bounds__(256) void pre_kernel(
        const float* __restrict__ h, const float* __restrict__ w1,
        const float* __restrict__ b1)
{
    __shared__ float w1s[128*64];   // 32KB
    __shared__ float hs[2][64];
    __shared__ float b1s[64];
    int t = threadIdx.x;
    int blk = blockIdx.x;
    u32 smb = smem_u32(w1s);
    #pragma unroll
    for (int q = 0; q < 8; q++)
        cpa16(smb + t*16 + q*4096, (const char*)w1 + t*16 + q*4096);
    CPA_COMMIT();
    if (t < 128) hs[t>>6][t&63] = h[blk*2*FF + t];
    if (t < 64)  b1s[t] = b1[t];
    CPA_WAIT(0);
    __syncthreads();

    int k = t & 63, r = t >> 6;
    int jj = r >> 1, part = r & 1;
    const float* wb = &w1s[part*64*64];
    const float* hv = hs[jj];
    float a0=0,a1=0,a2=0,a3=0;
    #pragma unroll 8
    for (int f = 0; f < 64; f += 4) {
        a0 += hv[f+0]*wb[(f+0)*64 + k];
        a1 += hv[f+1]*wb[(f+1)*64 + k];
        a2 += hv[f+2]*wb[(f+2)*64 + k];
        a3 += hv[f+3]*wb[(f+3)*64 + k];
    }
    float a = (a0+a1)+(a2+a3);
    int bi = blk*2 + jj, b = bi >> 8, j = bi & 255;
    if (part == 0) g_AT[(b*HH + k)*NN + j] = a;
    else           g_acci[bi*HH + k] = a + b1s[k];
}

// ---------------- kernel A: edge layer2 + sem, 8j x 8k tile, 128 thr --------
// grid: BB*NN*2 = 1024 (bi, half of 128 j), block 128.
__global__ __launch_bounds__(128) void edge_kernel(
        const float* __restrict__ x,
        const float* __restrict__ w1,
        const float* __restrict__ w2, const float* __restrict__ b2,
        const float* __restrict__ sw, const float* __restrict__ sb)
{
    int blk = blockIdx.x;
    int bi = blk >> 1, half = blk & 1;
    int b = bi >> 8, i = bi & 255;
    int t = threadIdx.x;
    int tx = t & 7, ty = t >> 3;           // k = tx*8, j = ty*8  (8 x 16 grid)

    __shared__ float hid[64*132];          // [k][j]; reused for sem partials
    __shared__ float acci_s[64];
    __shared__ float w1x_s[64];
    __shared__ float xnorm_s[128];
    __shared__ float ssw[256];
    __shared__ float ssb[4];

    if (t < 64) { acci_s[t] = g_acci[bi*HH + t]; w1x_s[t] = w1[128*HH + t]; }
    { ssw[t] = sw[t]; ssw[t+128] = sw[t+128]; }
    if (t < 4) ssb[t] = sb[t];
    {
        int j = half*128 + t;
        float dx = x[(b*NN + j)*3+0] - x[(b*NN + i)*3+0];
        float dy = x[(b*NN + j)*3+1] - x[(b*NN + i)*3+1];
        float dz = x[(b*NN + j)*3+2] - x[(b*NN + i)*3+2];
        xnorm_s[t] = sqrtf(dx*dx + dy*dy + dz*dz + EPSV);
    }
    __syncthreads();

    // ---- layer-1 elementwise: 128 threads, thread = (k, j-half of 64) ----
    {
        int k = t >> 1, jg = t & 1;
        float ac = acci_s[k], wx = w1x_s[k];
        const float* Arow = &g_AT[(b*HH + k)*NN + half*128];
        #pragma unroll
        for (int q = 0; q < 16; q++) {
            int jl = jg*64 + q*4;
            float4 av = *(const float4*)&Arow[jl];
            float4 xv = *(const float4*)&xnorm_s[jl];
            float4 hv;
            hv.x = silu_f(fmaf(xv.x, wx, av.x + ac));
            hv.y = silu_f(fmaf(xv.y, wx, av.y + ac));
            hv.z = silu_f(fmaf(xv.z, wx, av.z + ac));
            hv.w = silu_f(fmaf(xv.w, wx, av.w + ac));
            *(float4*)&hid[k*132 + jl] = hv;
        }
    }
    __syncthreads();

    // ---- layer 2: 8j x 8k per thread, j-pairs packed in u64 ----------------
    float eb[8][8];   // [j][k]
    {
        u64 acc[4][8];   // [j-pair][k]
        {
            float4 bva = *(const float4*)&b2[tx*8];
            float4 bvb = *(const float4*)&b2[tx*8+4];
            u64 bd[8];
            bd[0]=pack2(bva.x,bva.x); bd[1]=pack2(bva.y,bva.y);
            bd[2]=pack2(bva.z,bva.z); bd[3]=pack2(bva.w,bva.w);
            bd[4]=pack2(bvb.x,bvb.x); bd[5]=pack2(bvb.y,bvb.y);
            bd[6]=pack2(bvb.z,bvb.z); bd[7]=pack2(bvb.w,bvb.w);
            #pragma unroll
            for (int jp = 0; jp < 4; jp++)
                #pragma unroll
                for (int kk = 0; kk < 8; kk++) acc[jp][kk] = bd[kk];
        }
        #pragma unroll 2
        for (int kf = 0; kf < 64; kf++) {
            float4 wa = *(const float4*)&w2[kf*HH + tx*8];
            float4 wb2v = *(const float4*)&w2[kf*HH + tx*8 + 4];
            u64 wd0 = pack2(wa.x, wa.x),  wd1 = pack2(wa.y, wa.y);
            u64 wd2 = pack2(wa.z, wa.z),  wd3 = pack2(wa.w, wa.w);
            u64 wd4 = pack2(wb2v.x, wb2v.x), wd5 = pack2(wb2v.y, wb2v.y);
            u64 wd6 = pack2(wb2v.z, wb2v.z), wd7 = pack2(wb2v.w, wb2v.w);
            float4 a0 = *(float4*)&hid[kf*132 + ty*8];
            float4 a1 = *(float4*)&hid[kf*132 + ty*8 + 4];
            u64 ap0 = pack2(a0.x, a0.y), ap1 = pack2(a0.z, a0.w);
            u64 ap2 = pack2(a1.x, a1.y), ap3 = pack2(a1.z, a1.w);
            FMA2(acc[0][0],ap0,wd0); FMA2(acc[0][1],ap0,wd1); FMA2(acc[0][2],ap0,wd2); FMA2(acc[0][3],ap0,wd3);
            FMA2(acc[0][4],ap0,wd4); FMA2(acc[0][5],ap0,wd5); FMA2(acc[0][6],ap0,wd6); FMA2(acc[0][7],ap0,wd7);
            FMA2(acc[1][0],ap1,wd0); FMA2(acc[1][1],ap1,wd1); FMA2(acc[1][2],ap1,wd2); FMA2(acc[1][3],ap1,wd3);
            FMA2(acc[1][4],ap1,wd4); FMA2(acc[1][5],ap1,wd5); FMA2(acc[1][6],ap1,wd6); FMA2(acc[1][7],ap1,wd7);
            FMA2(acc[2][0],ap2,wd0); FMA2(acc[2][1],ap2,wd1); FMA2(acc[2][2],ap2,wd2); FMA2(acc[2][3],ap2,wd3);
            FMA2(acc[2][4],ap2,wd4); FMA2(acc[2][5],ap2,wd5); FMA2(acc[2][6],ap2,wd6); FMA2(acc[2][7],ap2,wd7);
            FMA2(acc[3][0],ap3,wd0); FMA2(acc[3][1],ap3,wd1); FMA2(acc[3][2],ap3,wd2); FMA2(acc[3][3],ap3,wd3);
            FMA2(acc[3][4],ap3,wd4); FMA2(acc[3][5],ap3,wd5); FMA2(acc[3][6],ap3,wd6); FMA2(acc[3][7],ap3,wd7);
        }
        #pragma unroll
        for (int jp = 0; jp < 4; jp++)
            #pragma unroll
            for (int kk = 0; kk < 8; kk++) {
                float2 p = unpack2(acc[jp][kk]);
                eb[jp*2+0][kk] = silu_f(p.x);
                eb[jp*2+1][kk] = silu_f(p.y);
            }
    }
    // store e to g_eT[bi][h][j]: 8 k rows x 8 j (two float4 each)
    #pragma unroll
    for (int kk = 0; kk < 8; kk++) {
        float4 e0 = make_float4(eb[0][kk], eb[1][kk], eb[2][kk], eb[3][kk]);
        float4 e1 = make_float4(eb[4][kk], eb[5][kk], eb[6][kk], eb[7][kk]);
        float* dst = &g_eT[(bi*HH + tx*8+kk)*NN + half*128 + ty*8];
        *(float4*)dst = e0;
        *(float4*)(dst+4) = e1;
    }
    __syncthreads();   // all GEMM reads of hid done

    // ---- sem logits: partials over k (split by tx, 8 groups) ----
    {
        float* sempart = hid;       // 8*128*4 = 4096 floats
        #pragma unroll
        for (int jj = 0; jj < 8; jj++) {
            float p0=0.f, p1=0.f, p2=0.f, p3=0.f;
            #pragma unroll
            for (int kk = 0; kk < 8; kk++) {
                float e = eb[jj][kk];
                const float* swr = &ssw[(tx*8+kk)*4];
                p0 += e*swr[0]; p1 += e*swr[1]; p2 += e*swr[2]; p3 += e*swr[3];
            }
            float* dst = &sempart[(tx*128 + ty*8+jj)*4];
            dst[0]=p0; dst[1]=p1; dst[2]=p2; dst[3]=p3;
        }
        __syncthreads();
        // reduce 8 partials: 512 items (128 j x 4 hd), 4 per thread
        #pragma unroll
        for (int q = 0; q < 4; q++) {
            int item = t*4 + q;
            int jl = item >> 2, hd = item & 3;
            float a = ssb[hd];
            #pragma unroll
            for (int r = 0; r < 8; r++) a += sempart[(r*128 + jl)*4 + hd];
            a = (a > 0.f) ? a : 0.2f*a;
            g_sem[(bi*NN + half*128 + jl)*HEADS + hd] = a;
        }
    }
}

// ---------------- kernel B: fused attention + aggregation (R9 version) ------
__global__ __launch_bounds__(256) void attagg_kernel(
        const float* __restrict__ x, const float* __restrict__ vmix,
        const float* __restrict__ log_gamma)
{
    __shared__ float sh_eT[64][132];
    __shared__ float sattT[4][260];
    __shared__ float uT[3][260];
    __shared__ float4 redbuf4[8];

    int bi = blockIdx.x;
    int b = bi >> 8, i = bi & 255;
    int t = threadIdx.x;

    {
        float4 lg = *(const float4*)log_gamma;
        float4 gm = make_float4(__expf(lg.x), __expf(lg.y), __expf(lg.z), __expf(lg.w));
        float dx = x[(b*NN+t)*3+0] - x[(b*NN+i)*3+0];
        float dy = x[(b*NN+t)*3+1] - x[(b*NN+i)*3+1];
        float dz = x[(b*NN+t)*3+2] - x[(b*NN+i)*3+2];
        float xn = sqrtf(dx*dx + dy*dy + dz*dz + EPSV);
        float diag = (t == i) ? INFV : 0.f;
        float xm = xn + diag;

        float4 l1 = make_float4(-xm*gm.x, -xm*gm.y, -xm*gm.z, -xm*gm.w);
        float4 m1 = blk_reduce4(l1, true, redbuf4);
        float4 e1 = make_float4(__expf(l1.x-m1.x), __expf(l1.y-m1.y), __expf(l1.z-m1.z), __expf(l1.w-m1.w));
        float4 s1 = blk_reduce4(e1, false, redbuf4);
        float4 eu = make_float4(__fdividef(e1.x,s1.x), __fdividef(e1.y,s1.y),
                                __fdividef(e1.z,s1.z), __fdividef(e1.w,s1.w));
        float4 sl = *(const float4*)&g_sem[(bi*NN + t)*HEADS];
        sl.x -= diag; sl.y -= diag; sl.z -= diag; sl.w -= diag;
        float4 m2 = blk_reduce4(sl, true, redbuf4);
        float4 e2 = make_float4(__expf(sl.x-m2.x), __expf(sl.y-m2.y), __expf(sl.z-m2.z), __expf(sl.w-m2.w));
        float4 s2 = blk_reduce4(e2, false, redbuf4);
        float4 se = make_float4(__fdividef(e2.x,s2.x), __fdividef(e2.y,s2.y),
                                __fdividef(e2.z,s2.z), __fdividef(e2.w,s2.w));
        float4 p = make_float4(eu.x*se.x, eu.y*se.y, eu.z*se.z, eu.w*se.w);
        float4 m3 = blk_reduce4(p, true, redbuf4);
        float4 e3 = make_float4(__expf(p.x-m3.x), __expf(p.y-m3.y), __expf(p.z-m3.z), __expf(p.w-m3.w));
        float4 s3 = blk_reduce4(e3, false, redbuf4);
        sattT[0][t] = __fdividef(e3.x,s3.x);
        sattT[1][t] = __fdividef(e3.y,s3.y);
        sattT[2][t] = __fdividef(e3.z,s3.z);
        sattT[3][t] = __fdividef(e3.w,s3.w);

        float inv = __fdividef(1.f, xn + EPSV);
        uT[0][t] = dx * inv;
        uT[1][t] = dy * inv;
        uT[2][t] = dz * inv;
    }
    __syncthreads();

    int c = t, hh = c >> 2, hd = c & 3;
    float agg = 0.f, cs0 = 0.f, cs1 = 0.f, cs2 = 0.f;

    for (int ch = 0; ch < 2; ch++) {
        const float* src = &g_eT[bi*HH*NN + ch*128];
        for (int idx = t; idx < 64*32; idx += 256) {
            int hr = idx >> 5, c4 = idx & 31;
            *(float4*)&sh_eT[hr][c4*4] = *(const float4*)&src[hr*NN + c4*4];
        }
        __syncthreads();
        #pragma unroll 4
        for (int q = 0; q < 32; q++) {
            float4 e4 = *(float4*)&sh_eT[hh][q*4];
            float4 a4 = *(float4*)&sattT[hd][ch*128 + q*4];
            float4 u0 = *(float4*)&uT[0][ch*128 + q*4];
            float4 u1 = *(float4*)&uT[1][ch*128 + q*4];
            float4 u2 = *(float4*)&uT[2][ch*128 + q*4];
            float w0 = e4.x*a4.x, w1 = e4.y*a4.y, w2 = e4.z*a4.z, w3 = e4.w*a4.w;
            agg += (w0 + w1) + (w2 + w3);
            cs0 += w0*u0.x + w1*u0.y + w2*u0.z + w3*u0.w;
            cs1 += w0*u1.x + w1*u1.y + w2*u1.z + w3*u1.w;
            cs2 += w0*u2.x + w1*u2.y + w2*u2.z + w3*u2.w;
        }
        __syncthreads();
    }

    const float inv_n = 1.f / (float)NN;
    cs0 *= inv_n; cs1 *= inv_n; cs2 *= inv_n;

    g_hagg[bi*CC + c]     = agg;
    g_combnorm[bi*CC + c] = cs0*cs0 + cs1*cs1 + cs2*cs2;

    float* red = (float*)sh_eT;
    float vm = vmix[c];
    float d0 = blk_sum256(vm * cs0, red);
    float d1 = blk_sum256(vm * cs1, red);
    float d2 = blk_sum256(vm * cs2, red);
    if (c == 0) {
        g_deltav[bi*3 + 0] = d0;
        g_deltav[bi*3 + 1] = d1;
        g_deltav[bi*3 + 2] = d2;
    }
}

// ---------------- kernel C: node MLPs — cp.async pipelined (R9 version) -----
#define O_PW1  0        // 16384
#define O_PW2  16384    // 4096
#define O_NW1  20480    // 24576
#define O_NW2  45056    // 4096
#define O_PB1  49152
#define O_PB2  49216
#define O_NB1  49280
#define O_NB2  49344
#define O_CNT  49408    // 1024
#define O_NACT 50432    // 1536
#define O_HID  51968    // 256
#define O_HNEW 52224    // 256
#define O_SBUF 52480    // 2048
#define O_MISC 54528    // 16
#define NODE_SMEM_FLOATS 54544

__global__ __launch_bounds__(512) void node_kernel(
        const float* __restrict__ h, const float* __restrict__ x,
        const float* __restrict__ v,
        const float* __restrict__ pw1, const float* __restrict__ pb1,
        const float* __restrict__ pw2, const float* __restrict__ pb2,
        const float* __restrict__ nw1, const float* __restrict__ nb1,
        const float* __restrict__ nw2, const float* __restrict__ nb2,
        const float* __restrict__ vw1, const float* __restrict__ vb1,
        const float* __restrict__ vw2,
        float* __restrict__ out)
{
    int bi = blockIdx.x;
    int t = threadIdx.x;
    int k = t & 63, r = t >> 6;
    u32 smb = smem_u32(sm);

    for (int idx = t*16; idx < 65536; idx += 512*16)
        cpa16(smb + O_PW1*4 + idx, (const char*)pw1 + idx);
    if (t < 16) cpa16(smb + O_PB1*4 + t*16, (const char*)pb1 + t*16);
    CPA_COMMIT();
    for (int idx = t*16; idx < 16384; idx += 512*16)
        cpa16(smb + O_PW2*4 + idx, (const char*)pw2 + idx);
    if (t < 16) cpa16(smb + O_PB2*4 + t*16, (const char*)pb2 + t*16);
    CPA_COMMIT();
    for (int idx = t*16; idx < 98304; idx += 512*16)
        cpa16(smb + O_NW1*4 + idx, (const char*)nw1 + idx);
    if (t < 16) cpa16(smb + O_NB1*4 + t*16, (const char*)nb1 + t*16);
    CPA_COMMIT();
    for (int idx = t*16; idx < 16384; idx += 512*16)
        cpa16(smb + O_NW2*4 + idx, (const char*)nw2 + idx);
    if (t < 16) cpa16(smb + O_NB2*4 + t*16, (const char*)nb2 + t*16);
    CPA_COMMIT();

    if (t < 256) {
        int kk = t & 63, node = t >> 6;
        #pragma unroll
        for (int q = 0; q < 4; q++) {
            int u = kk + q*64;
            sm[O_CNT  + u*4 + node]      = g_combnorm[(bi*4 + node)*CC + u];
            sm[O_NACT + (64+u)*4 + node] = g_hagg[(bi*4 + node)*CC + u];
        }
        sm[O_NACT + kk*4 + node] = h[(bi*4 + node)*FF + kk];
    }

    CPA_WAIT(3);
    __syncthreads();

    // post1
    {
        float a0=0,a1=0,a2=0,a3=0;
        #pragma unroll 8
        for (int uu = 0; uu < 32; uu++) {
            int u = r*32 + uu;
            float w = sm[O_PW1 + u*HH + k];
            float4 a4 = *(float4*)&sm[O_CNT + u*4];
            a0 += a4.x*w; a1 += a4.y*w; a2 += a4.z*w; a3 += a4.w*w;
        }
        sm[O_SBUF+(r*4+0)*64+k]=a0; sm[O_SBUF+(r*4+1)*64+k]=a1;
        sm[O_SBUF+(r*4+2)*64+k]=a2; sm[O_SBUF+(r*4+3)*64+k]=a3;
    }
    CPA_WAIT(2);
    __syncthreads();
    if (t < 256) {
        int kk = t & 63, node = t >> 6;
        float s = sm[O_PB1+kk];
        #pragma unroll
        for (int q = 0; q < 8; q++) s += sm[O_SBUF+(q*4+node)*64+kk];
        sm[O_HID + kk*4+node] = silu_f(s);
    }
    __syncthreads();

    // post2
    {
        float a0=0,a1=0,a2=0,a3=0;
        #pragma unroll
        for (int uu = 0; uu < 8; uu++) {
            int u = r*8 + uu;
            float w = sm[O_PW2 + u*HH + k];
            float4 a4 = *(float4*)&sm[O_HID + u*4];
            a0 += a4.x*w; a1 += a4.y*w; a2 += a4.z*w; a3 += a4.w*w;
        }
        sm[O_SBUF+(r*4+0)*64+k]=a0; sm[O_SBUF+(r*4+1)*64+k]=a1;
        sm[O_SBUF+(r*4+2)*64+k]=a2; sm[O_SBUF+(r*4+3)*64+k]=a3;
    }
    CPA_WAIT(1);
    __syncthreads();
    if (t < 256) {
        int kk = t & 63, node = t >> 6;
        float s = sm[O_PB2+kk];
        #pragma unroll
        for (int q = 0; q < 8; q++) s += sm[O_SBUF+(q*4+node)*64+kk];
        sm[O_NACT + (320+kk)*4+node] = silu_f(s);
    }
    __syncthreads();

    // node1
    {
        float a0=0,a1=0,a2=0,a3=0;
        #pragma unroll 8
        for (int uu = 0; uu < 48; uu++) {
            int u = r*48 + uu;
            float w = sm[O_NW1 + u*HH + k];
            float4 a4 = *(float4*)&sm[O_NACT + u*4];
            a0 += a4.x*w; a1 += a4.y*w; a2 += a4.z*w; a3 += a4.w*w;
        }
        sm[O_SBUF+(r*4+0)*64+k]=a0; sm[O_SBUF+(r*4+1)*64+k]=a1;
        sm[O_SBUF+(r*4+2)*64+k]=a2; sm[O_SBUF+(r*4+3)*64+k]=a3;
    }
    CPA_WAIT(0);
    __syncthreads();
    if (t < 256) {
        int kk = t & 63, node = t >> 6;
        float s = sm[O_NB1+kk];
        #pragma unroll
        for (int q = 0; q < 8; q++) s += sm[O_SBUF+(q*4+node)*64+kk];
        sm[O_HID + kk*4+node] = silu_f(s);
    }
    __syncthreads();

    // node2 + residual
    {
        float a0=0,a1=0,a2=0,a3=0;
        #pragma unroll
        for (int uu = 0; uu < 8; uu++) {
            int u = r*8 + uu;
            float w = sm[O_NW2 + u*HH + k];
            float4 a4 = *(float4*)&sm[O_HID + u*4];
            a0 += a4.x*w; a1 += a4.y*w; a2 += a4.z*w; a3 += a4.w*w;
        }
        sm[O_SBUF+(r*4+0)*64+k]=a0; sm[O_SBUF+(r*4+1)*64+k]=a1;
        sm[O_SBUF+(r*4+2)*64+k]=a2; sm[O_SBUF+(r*4+3)*64+k]=a3;
    }
    __syncthreads();
    if (t < 256) {
        int kk = t & 63, node = t >> 6;
        float s = sm[O_NB2+kk];
        #pragma unroll
        for (int q = 0; q < 8; q++) s += sm[O_SBUF+(q*4+node)*64+kk];
        float hn = sm[O_NACT + kk*4+node] + silu_f(s);
        sm[O_HNEW + kk*4+node] = hn;
        out[(bi*4+node)*FF + kk] = hn;
    }
    __syncthreads();

    // vel
    {
        float a0=0,a1=0,a2=0,a3=0;
        #pragma unroll
        for (int uu = 0; uu < 8; uu++) {
            int u = r*8 + uu;
            float w = __ldg(&vw1[u*HH + k]);
            float4 a4 = *(float4*)&sm[O_HNEW + u*4];
            a0 += a4.x*w; a1 += a4.y*w; a2 += a4.z*w; a3 += a4.w*w;
        }
        sm[O_SBUF+(r*4+0)*64+k]=a0; sm[O_SBUF+(r*4+1)*64+k]=a1;
        sm[O_SBUF+(r*4+2)*64+k]=a2; sm[O_SBUF+(r*4+3)*64+k]=a3;
    }
    __syncthreads();
    if (t < 256) {
        int kk = t & 63, node = t >> 6;
        float s = 0.f;
        #pragma unroll
        for (int q = 0; q < 8; q++) s += sm[O_SBUF+(q*4+node)*64+kk];
        float sv = silu_f(s + __ldg(&vb1[kk])) * __ldg(&vw2[kk]);
        sv = warpsumf(sv);
        if ((t & 31) == 0) sm[O_MISC + 4 + (t >> 5)] = sv;
    }
    __syncthreads();
    if (t < 4) sm[O_MISC + t] = sm[O_MISC+4 + t*2] + sm[O_MISC+4 + t*2+1];
    __syncthreads();
    if (t < 12) {
        int nd = t / 3, d = t % 3;
        int gi = bi*4 + nd;
        float vv = v[gi*3 + d];
        float vn = g_deltav[gi*3 + d] + sm[O_MISC + nd]*vv;
        out[BB*NN*FF + gi*3 + d]            = x[gi*3 + d] + vn;
        out[BB*NN*FF + BB*NN*3 + gi*3 + d]  = vn;
    }
}

// ---------------------------------------------------------------------------
extern "C" void kernel_launch(void* const* d_in, const int* in_sizes, int n_in,
                              void* d_out, int out_size)
{
    const float* h        = (const float*)d_in[0];
    const float* x        = (const float*)d_in[1];
    const float* v        = (const float*)d_in[2];
    const float* edge_w1  = (const float*)d_in[3];
    const float* edge_b1  = (const float*)d_in[4];
    const float* edge_w2  = (const float*)d_in[5];
    const float* edge_b2  = (const float*)d_in[6];
    const float* sem_w    = (const float*)d_in[7];
    const float* sem_b    = (const float*)d_in[8];
    const float* post_w1  = (const float*)d_in[9];
    const float* post_b1  = (const float*)d_in[10];
    const float* post_w2  = (const float*)d_in[11];
    const float* post_b2  = (const float*)d_in[12];
    const float* node_w1  = (const float*)d_in[13];
    const float* node_b1  = (const float*)d_in[14];
    const float* node_w2  = (const float*)d_in[15];
    const float* node_b2  = (const float*)d_in[16];
    const float* vel_w1   = (const float*)d_in[17];
    const float* vel_b1   = (const float*)d_in[18];
    const float* vel_w2   = (const float*)d_in[19];
    const float* vmix_w   = (const float*)d_in[20];
    const float* log_gamma= (const float*)d_in[21];
    float* out = (float*)d_out;

    static int cfg_done = 0;
    if (!cfg_done) {
        cudaFuncSetAttribute(node_kernel,
                             cudaFuncAttributeMaxDynamicSharedMemorySize,
                             NODE_SMEM_FLOATS * (int)sizeof(float));
        cfg_done = 1;
    }

    pre_kernel<<<BB*NN/2, 256>>>(h, edge_w1, edge_b1);
    edge_kernel<<<BB*NN*2, 128>>>(x, edge_w1, edge_w2, edge_b2, sem_w, sem_b);
    attagg_kernel<<<BB*NN, 256>>>(x, vmix_w, log_gamma);
    node_kernel<<<BB*NN/4, 512, NODE_SMEM_FLOATS * sizeof(float)>>>(
                                  h, x, v,
                                  post_w1, post_b1, post_w2, post_b2,
                                  node_w1, node_b1, node_w2, node_b2,
                                  vel_w1, vel_b1, vel_w2, out);
}

// round 17
// speedup vs baseline: 1.2405x; 1.0240x over previous
#include <cuda_runtime.h>
#include <math.h>

#define BB 2
#define NN 256
#define FF 64
#define HH 64
#define HEADS 4
#define CC 256
#define EPSV 1e-5f
#define INFV 1e5f

typedef unsigned long long u64;
typedef unsigned int u32;

// ---------------- scratch (device globals) ----------------------------------
__device__ float g_eT[BB*NN*HH*NN];         // [bi][h][j]
__device__ float g_sem[BB*NN*NN*HEADS];
__device__ float g_AT[BB*HH*NN];            // A[b][k][j] = h_j @ W1[0:64]
__device__ float g_acci[BB*NN*HH];          // acci[bi][k] = b1 + h_i @ W1[64:128]
__device__ float g_combnorm[BB*NN*CC];
__device__ float g_hagg[BB*NN*CC];
__device__ float g_deltav[BB*NN*3];

__device__ __forceinline__ float silu_f(float v){ return __fdividef(v, 1.f + __expf(-v)); }

__device__ __forceinline__ u64 pack2(float lo, float hi){
    u64 r; unsigned lu = __float_as_uint(lo), hu = __float_as_uint(hi);
    asm("mov.b64 %0, {%1, %2};" : "=l"(r) : "r"(lu), "r"(hu));
    return r;
}
__device__ __forceinline__ float2 unpack2(u64 v){
    unsigned lu, hu;
    asm("mov.b64 {%0, %1}, %2;" : "=r"(lu), "=r"(hu) : "l"(v));
    return make_float2(__uint_as_float(lu), __uint_as_float(hu));
}
#define FMA2(acc,a,b) asm("fma.rn.f32x2 %0, %1, %2, %3;" : "=l"(acc) : "l"(a), "l"(b), "l"(acc))

__device__ __forceinline__ u32 smem_u32(const void* p){
    u32 a;
    asm("{ .reg .u64 tmp; cvta.to.shared.u64 tmp, %1; cvt.u32.u64 %0, tmp; }"
        : "=r"(a) : "l"(p));
    return a;
}
__device__ __forceinline__ void cpa16(u32 dst, const void* src){
    asm volatile("cp.async.cg.shared.global [%0], [%1], 16;" :: "r"(dst), "l"(src));
}
#define CPA_COMMIT()  asm volatile("cp.async.commit_group;" ::: "memory")
#define CPA_WAIT(N)   asm volatile("cp.async.wait_group %0;" :: "n"(N) : "memory")

extern __shared__ float sm[];

__device__ __forceinline__ float warpmaxf(float v){
    #pragma unroll
    for (int s=16;s;s>>=1) v = fmaxf(v, __shfl_xor_sync(0xffffffffu, v, s));
    return v;
}
__device__ __forceinline__ float warpsumf(float v){
    #pragma unroll
    for (int s=16;s;s>>=1) v += __shfl_xor_sync(0xffffffffu, v, s);
    return v;
}

// ---------------- kernel P: precompute A and acci (smem-staged W1) ----------
__global__ __launch_bounds__(256) void pre_kernel(
        const float* __restrict__ h, const float* __restrict__ w1,
        const float* __restrict__ b1)
{
    __shared__ float w1s[128*64];   // 32KB
    __shared__ float hs[2][64];
    __shared__ float b1s[64];
    int t = threadIdx.x;
    int blk = blockIdx.x;
    u32 smb = smem_u32(w1s);
    #pragma unroll
    for (int q = 0; q < 8; q++)
        cpa16(smb + t*16 + q*4096, (const char*)w1 + t*16 + q*4096);
    CPA_COMMIT();
    if (t < 128) hs[t>>6][t&63] = h[blk*2*FF + t];
    if (t < 64)  b1s[t] = b1[t];
    CPA_WAIT(0);
    __syncthreads();

    int k = t & 63, r = t >> 6;
    int jj = r >> 1, part = r & 1;
    const float* wb = &w1s[part*64*64];
    const float* hv = hs[jj];
    float a0=0,a1=0,a2=0,a3=0;
    #pragma unroll 8
    for (int f = 0; f < 64; f += 4) {
        a0 += hv[f+0]*wb[(f+0)*64 + k];
        a1 += hv[f+1]*wb[(f+1)*64 + k];
        a2 += hv[f+2]*wb[(f+2)*64 + k];
        a3 += hv[f+3]*wb[(f+3)*64 + k];
    }
    float a = (a0+a1)+(a2+a3);
    int bi = blk*2 + jj, b = bi >> 8, j = bi & 255;
    if (part == 0) g_AT[(b*HH + k)*NN + j] = a;
    else           g_acci[bi*HH + k] = a + b1s[k];
}

// ---------------- kernel A: edge layer2 + sem, 8j x 8k tile, 128 thr --------
// grid: BB*NN*2 = 1024 (bi, half of 128 j), block 128.  (identical to R16)
__global__ __launch_bounds__(128) void edge_kernel(
        const float* __restrict__ x,
        const float* __restrict__ w1,
        const float* __restrict__ w2, const float* __restrict__ b2,
        const float* __restrict__ sw, const float* __restrict__ sb)
{
    int blk = blockIdx.x;
    int bi = blk >> 1, half = blk & 1;
    int b = bi >> 8, i = bi & 255;
    int t = threadIdx.x;
    int tx = t & 7, ty = t >> 3;           // k = tx*8, j = ty*8  (8 x 16 grid)

    __shared__ float hid[64*132];          // [k][j]; reused for sem partials
    __shared__ float acci_s[64];
    __shared__ float w1x_s[64];
    __shared__ float xnorm_s[128];
    __shared__ float ssw[256];
    __shared__ float ssb[4];

    if (t < 64) { acci_s[t] = g_acci[bi*HH + t]; w1x_s[t] = w1[128*HH + t]; }
    { ssw[t] = sw[t]; ssw[t+128] = sw[t+128]; }
    if (t < 4) ssb[t] = sb[t];
    {
        int j = half*128 + t;
        float dx = x[(b*NN + j)*3+0] - x[(b*NN + i)*3+0];
        float dy = x[(b*NN + j)*3+1] - x[(b*NN + i)*3+1];
        float dz = x[(b*NN + j)*3+2] - x[(b*NN + i)*3+2];
        xnorm_s[t] = sqrtf(dx*dx + dy*dy + dz*dz + EPSV);
    }
    __syncthreads();

    // ---- layer-1 elementwise ----
    {
        int k = t >> 1, jg = t & 1;
        float ac = acci_s[k], wx = w1x_s[k];
        const float* Arow = &g_AT[(b*HH + k)*NN + half*128];
        #pragma unroll
        for (int q = 0; q < 16; q++) {
            int jl = jg*64 + q*4;
            float4 av = *(const float4*)&Arow[jl];
            float4 xv = *(const float4*)&xnorm_s[jl];
            float4 hv;
            hv.x = silu_f(fmaf(xv.x, wx, av.x + ac));
            hv.y = silu_f(fmaf(xv.y, wx, av.y + ac));
            hv.z = silu_f(fmaf(xv.z, wx, av.z + ac));
            hv.w = silu_f(fmaf(xv.w, wx, av.w + ac));
            *(float4*)&hid[k*132 + jl] = hv;
        }
    }
    __syncthreads();

    // ---- layer 2: 8j x 8k per thread, j-pairs packed in u64 ----------------
    float eb[8][8];
    {
        u64 acc[4][8];
        {
            float4 bva = *(const float4*)&b2[tx*8];
            float4 bvb = *(const float4*)&b2[tx*8+4];
            u64 bd[8];
            bd[0]=pack2(bva.x,bva.x); bd[1]=pack2(bva.y,bva.y);
            bd[2]=pack2(bva.z,bva.z); bd[3]=pack2(bva.w,bva.w);
            bd[4]=pack2(bvb.x,bvb.x); bd[5]=pack2(bvb.y,bvb.y);
            bd[6]=pack2(bvb.z,bvb.z); bd[7]=pack2(bvb.w,bvb.w);
            #pragma unroll
            for (int jp = 0; jp < 4; jp++)
                #pragma unroll
                for (int kk = 0; kk < 8; kk++) acc[jp][kk] = bd[kk];
        }
        #pragma unroll 2
        for (int kf = 0; kf < 64; kf++) {
            float4 wa = *(const float4*)&w2[kf*HH + tx*8];
            float4 wb2v = *(const float4*)&w2[kf*HH + tx*8 + 4];
            u64 wd0 = pack2(wa.x, wa.x),  wd1 = pack2(wa.y, wa.y);
            u64 wd2 = pack2(wa.z, wa.z),  wd3 = pack2(wa.w, wa.w);
            u64 wd4 = pack2(wb2v.x, wb2v.x), wd5 = pack2(wb2v.y, wb2v.y);
            u64 wd6 = pack2(wb2v.z, wb2v.z), wd7 = pack2(wb2v.w, wb2v.w);
            float4 a0 = *(float4*)&hid[kf*132 + ty*8];
            float4 a1 = *(float4*)&hid[kf*132 + ty*8 + 4];
            u64 ap0 = pack2(a0.x, a0.y), ap1 = pack2(a0.z, a0.w);
            u64 ap2 = pack2(a1.x, a1.y), ap3 = pack2(a1.z, a1.w);
            FMA2(acc[0][0],ap0,wd0); FMA2(acc[0][1],ap0,wd1); FMA2(acc[0][2],ap0,wd2); FMA2(acc[0][3],ap0,wd3);
            FMA2(acc[0][4],ap0,wd4); FMA2(acc[0][5],ap0,wd5); FMA2(acc[0][6],ap0,wd6); FMA2(acc[0][7],ap0,wd7);
            FMA2(acc[1][0],ap1,wd0); FMA2(acc[1][1],ap1,wd1); FMA2(acc[1][2],ap1,wd2); FMA2(acc[1][3],ap1,wd3);
            FMA2(acc[1][4],ap1,wd4); FMA2(acc[1][5],ap1,wd5); FMA2(acc[1][6],ap1,wd6); FMA2(acc[1][7],ap1,wd7);
            FMA2(acc[2][0],ap2,wd0); FMA2(acc[2][1],ap2,wd1); FMA2(acc[2][2],ap2,wd2); FMA2(acc[2][3],ap2,wd3);
            FMA2(acc[2][4],ap2,wd4); FMA2(acc[2][5],ap2,wd5); FMA2(acc[2][6],ap2,wd6); FMA2(acc[2][7],ap2,wd7);
            FMA2(acc[3][0],ap3,wd0); FMA2(acc[3][1],ap3,wd1); FMA2(acc[3][2],ap3,wd2); FMA2(acc[3][3],ap3,wd3);
            FMA2(acc[3][4],ap3,wd4); FMA2(acc[3][5],ap3,wd5); FMA2(acc[3][6],ap3,wd6); FMA2(acc[3][7],ap3,wd7);
        }
        #pragma unroll
        for (int jp = 0; jp < 4; jp++)
            #pragma unroll
            for (int kk = 0; kk < 8; kk++) {
                float2 p = unpack2(acc[jp][kk]);
                eb[jp*2+0][kk] = silu_f(p.x);
                eb[jp*2+1][kk] = silu_f(p.y);
            }
    }
    #pragma unroll
    for (int kk = 0; kk < 8; kk++) {
        float4 e0 = make_float4(eb[0][kk], eb[1][kk], eb[2][kk], eb[3][kk]);
        float4 e1 = make_float4(eb[4][kk], eb[5][kk], eb[6][kk], eb[7][kk]);
        float* dst = &g_eT[(bi*HH + tx*8+kk)*NN + half*128 + ty*8];
        *(float4*)dst = e0;
        *(float4*)(dst+4) = e1;
    }
    __syncthreads();

    // ---- sem logits ----
    {
        float* sempart = hid;
        #pragma unroll
        for (int jj = 0; jj < 8; jj++) {
            float p0=0.f, p1=0.f, p2=0.f, p3=0.f;
            #pragma unroll
            for (int kk = 0; kk < 8; kk++) {
                float e = eb[jj][kk];
                const float* swr = &ssw[(tx*8+kk)*4];
                p0 += e*swr[0]; p1 += e*swr[1]; p2 += e*swr[2]; p3 += e*swr[3];
            }
            float* dst = &sempart[(tx*128 + ty*8+jj)*4];
            dst[0]=p0; dst[1]=p1; dst[2]=p2; dst[3]=p3;
        }
        __syncthreads();
        #pragma unroll
        for (int q = 0; q < 4; q++) {
            int item = t*4 + q;
            int jl = item >> 2, hd = item & 3;
            float a = ssb[hd];
            #pragma unroll
            for (int r = 0; r < 8; r++) a += sempart[(r*128 + jl)*4 + hd];
            a = (a > 0.f) ? a : 0.2f*a;
            g_sem[(bi*NN + half*128 + jl)*HEADS + hd] = a;
        }
    }
}

// ---------------- kernel B: attention + aggregation, 256 thr, low-sync ------
// cp.async prefetch of eT; 4 interleaved reduction rounds; single agg pass.
#define A_ET    0        // 64*260 = 16640
#define A_SATT  16640    // 4*260 = 1040
#define A_UT    17680    // 3*260 = 780
#define A_RED   18460    // 64 (8 warps x 8)
#define A_WPART 18524    // 24 (8 warps x 3)
#define ATT_SMEM_FLOATS 18560

__global__ __launch_bounds__(256) void attagg_kernel(
        const float* __restrict__ x, const float* __restrict__ vmix,
        const float* __restrict__ log_gamma)
{
    int bi = blockIdx.x;
    int b = bi >> 8, i = bi & 255;
    int t = threadIdx.x;
    u32 smb = smem_u32(sm);

    // ---- prefetch full eT tile (64 x 256 -> rows padded to 260) ----
    {
        const char* src = (const char*)&g_eT[bi*HH*NN];
        #pragma unroll
        for (int q = 0; q < 16; q++) {
            int idx = t + q*256;              // 0..4095 16B-chunks
            int hr = idx >> 6, c16 = idx & 63;
            cpa16(smb + (u32)(A_ET + hr*260)*4u + c16*16, src + hr*1024 + c16*16);
        }
        CPA_COMMIT();
    }

    // ---- setup: geometry + 8 logits ----
    float l1s[8], v8[8];
    float diag;
    {
        float4 lg = *(const float4*)log_gamma;
        float4 gm = make_float4(__expf(lg.x), __expf(lg.y), __expf(lg.z), __expf(lg.w));
        float dx = x[(b*NN+t)*3+0] - x[(b*NN+i)*3+0];
        float dy = x[(b*NN+t)*3+1] - x[(b*NN+i)*3+1];
        float dz = x[(b*NN+t)*3+2] - x[(b*NN+i)*3+2];
        float xn = sqrtf(dx*dx + dy*dy + dz*dz + EPSV);
        float inv = __fdividef(1.f, xn + EPSV);
        sm[A_UT + 0*260 + t] = dx * inv;
        sm[A_UT + 1*260 + t] = dy * inv;
        sm[A_UT + 2*260 + t] = dz * inv;
        diag = (t == i) ? INFV : 0.f;
        float xm = xn + diag;
        l1s[0] = -xm*gm.x; l1s[1] = -xm*gm.y; l1s[2] = -xm*gm.z; l1s[3] = -xm*gm.w;
        float4 sl = *(const float4*)&g_sem[(bi*NN + t)*HEADS];
        l1s[4] = sl.x - diag; l1s[5] = sl.y - diag; l1s[6] = sl.z - diag; l1s[7] = sl.w - diag;
    }
    int w = t >> 5;

    // ---- reduction round 1: max of 8 logits ----
    #pragma unroll
    for (int q = 0; q < 8; q++) v8[q] = warpmaxf(l1s[q]);
    if ((t & 31) == 0) {
        #pragma unroll
        for (int q = 0; q < 8; q++) sm[A_RED + w*8 + q] = v8[q];
    }
    __syncthreads();
    float mx[8], ex[8];
    #pragma unroll
    for (int q = 0; q < 8; q++) {
        float m = sm[A_RED + q];
        #pragma unroll
        for (int ww = 1; ww < 8; ww++) m = fmaxf(m, sm[A_RED + ww*8 + q]);
        mx[q] = m;
        ex[q] = __expf(l1s[q] - m);
    }
    __syncthreads();
    // ---- reduction round 2: sums of 8 exps ----
    #pragma unroll
    for (int q = 0; q < 8; q++) v8[q] = warpsumf(ex[q]);
    if ((t & 31) == 0) {
        #pragma unroll
        for (int q = 0; q < 8; q++) sm[A_RED + w*8 + q] = v8[q];
    }
    __syncthreads();
    float4 p4;
    {
        float s[8];
        #pragma unroll
        for (int q = 0; q < 8; q++) {
            float v = sm[A_RED + q];
            #pragma unroll
            for (int ww = 1; ww < 8; ww++) v += sm[A_RED + ww*8 + q];
            s[q] = v;
        }
        p4.x = __fdividef(ex[0], s[0]) * __fdividef(ex[4], s[4]);
        p4.y = __fdividef(ex[1], s[1]) * __fdividef(ex[5], s[5]);
        p4.z = __fdividef(ex[2], s[2]) * __fdividef(ex[6], s[6]);
        p4.w = __fdividef(ex[3], s[3]) * __fdividef(ex[7], s[7]);
    }
    __syncthreads();
    // ---- reduction round 3: max of combined product ----
    v8[0]=warpmaxf(p4.x); v8[1]=warpmaxf(p4.y); v8[2]=warpmaxf(p4.z); v8[3]=warpmaxf(p4.w);
    if ((t & 31) == 0) {
        #pragma unroll
        for (int q = 0; q < 4; q++) sm[A_RED + w*8 + q] = v8[q];
    }
    __syncthreads();
    float4 e4v;
    {
        float m[4];
        #pragma unroll
        for (int q = 0; q < 4; q++) {
            float v = sm[A_RED + q];
            #pragma unroll
            for (int ww = 1; ww < 8; ww++) v = fmaxf(v, sm[A_RED + ww*8 + q]);
            m[q] = v;
        }
        e4v.x = __expf(p4.x - m[0]); e4v.y = __expf(p4.y - m[1]);
        e4v.z = __expf(p4.z - m[2]); e4v.w = __expf(p4.w - m[3]);
    }
    __syncthreads();
    // ---- reduction round 4: sum of final exps ----
    v8[0]=warpsumf(e4v.x); v8[1]=warpsumf(e4v.y); v8[2]=warpsumf(e4v.z); v8[3]=warpsumf(e4v.w);
    if ((t & 31) == 0) {
        #pragma unroll
        for (int q = 0; q < 4; q++) sm[A_RED + w*8 + q] = v8[q];
    }
    CPA_WAIT(0);               // eT tile resident before agg
    __syncthreads();
    {
        float s[4];
        #pragma unroll
        for (int q = 0; q < 4; q++) {
            float v = sm[A_RED + q];
            #pragma unroll
            for (int ww = 1; ww < 8; ww++) v += sm[A_RED + ww*8 + q];
            s[q] = v;
        }
        sm[A_SATT + 0*260 + t] = __fdividef(e4v.x, s[0]);
        sm[A_SATT + 1*260 + t] = __fdividef(e4v.y, s[1]);
        sm[A_SATT + 2*260 + t] = __fdividef(e4v.z, s[2]);
        sm[A_SATT + 3*260 + t] = __fdividef(e4v.w, s[3]);
    }
    __syncthreads();

    // ---- aggregation: single pass, all smem ----
    {
        int c = t, hh = c >> 2, hd = c & 3;
        float agg = 0.f, cs0 = 0.f, cs1 = 0.f, cs2 = 0.f;
        const float* erow = &sm[A_ET + hh*260];
        const float* arow = &sm[A_SATT + hd*260];
        const float* u0r = &sm[A_UT + 0*260];
        const float* u1r = &sm[A_UT + 1*260];
        const float* u2r = &sm[A_UT + 2*260];
        #pragma unroll 4
        for (int q = 0; q < 64; q++) {
            float4 e4 = *(const float4*)&erow[q*4];
            float4 a4 = *(const float4*)&arow[q*4];
            float4 u0 = *(const float4*)&u0r[q*4];
            float4 u1 = *(const float4*)&u1r[q*4];
            float4 u2 = *(const float4*)&u2r[q*4];
            float w0 = e4.x*a4.x, w1 = e4.y*a4.y, w2 = e4.z*a4.z, w3 = e4.w*a4.w;
            agg += (w0 + w1) + (w2 + w3);
            cs0 += w0*u0.x + w1*u0.y + w2*u0.z + w3*u0.w;
            cs1 += w0*u1.x + w1*u1.y + w2*u1.z + w3*u1.w;
            cs2 += w0*u2.x + w1*u2.y + w2*u2.z + w3*u2.w;
        }
        const float inv_n = 1.f / (float)NN;
        cs0 *= inv_n; cs1 *= inv_n; cs2 *= inv_n;
        g_hagg[bi*CC + c]     = agg;
        g_combnorm[bi*CC + c] = cs0*cs0 + cs1*cs1 + cs2*cs2;

        float vm = vmix[c];
        float d0 = warpsumf(vm*cs0);
        float d1 = warpsumf(vm*cs1);
        float d2 = warpsumf(vm*cs2);
        if ((t & 31) == 0) {
            sm[A_WPART + w*3 + 0] = d0;
            sm[A_WPART + w*3 + 1] = d1;
            sm[A_WPART + w*3 + 2] = d2;
        }
    }
    __syncthreads();
    if (t < 3) {
        float s = 0.f;
        #pragma unroll
        for (int ww = 0; ww < 8; ww++) s += sm[A_WPART + ww*3 + t];
        g_deltav[bi*3 + t] = s;
    }
}

// ---------------- kernel C: node MLPs — cp.async pipelined (R9 version) -----
#define O_PW1  0        // 16384
#define O_PW2  16384    // 4096
#define O_NW1  20480    // 24576
#define O_NW2  45056    // 4096
#define O_PB1  49152
#define O_PB2  49216
#define O_NB1  49280
#define O_NB2  49344
#define O_CNT  49408    // 1024
#define O_NACT 50432    // 1536
#define O_HID  51968    // 256
#define O_HNEW 52224    // 256
#define O_SBUF 52480    // 2048
#define O_MISC 54528    // 16
#define NODE_SMEM_FLOATS 54544

__global__ __launch_bounds__(512) void node_kernel(
        const float* __restrict__ h, const float* __restrict__ x,
        const float* __restrict__ v,
        const float* __restrict__ pw1, const float* __restrict__ pb1,
        const float* __restrict__ pw2, const float* __restrict__ pb2,
        const float* __restrict__ nw1, const float* __restrict__ nb1,
        const float* __restrict__ nw2, const float* __restrict__ nb2,
        const float* __restrict__ vw1, const float* __restrict__ vb1,
        const float* __restrict__ vw2,
        float* __restrict__ out)
{
    int bi = blockIdx.x;
    int t = threadIdx.x;
    int k = t & 63, r = t >> 6;
    u32 smb = smem_u32(sm);

    for (int idx = t*16; idx < 65536; idx += 512*16)
        cpa16(smb + O_PW1*4 + idx, (const char*)pw1 + idx);
    if (t < 16) cpa16(smb + O_PB1*4 + t*16, (const char*)pb1 + t*16);
    CPA_COMMIT();
    for (int idx = t*16; idx < 16384; idx += 512*16)
        cpa16(smb + O_PW2*4 + idx, (const char*)pw2 + idx);
    if (t < 16) cpa16(smb + O_PB2*4 + t*16, (const char*)pb2 + t*16);
    CPA_COMMIT();
    for (int idx = t*16; idx < 98304; idx += 512*16)
        cpa16(smb + O_NW1*4 + idx, (const char*)nw1 + idx);
    if (t < 16) cpa16(smb + O_NB1*4 + t*16, (const char*)nb1 + t*16);
    CPA_COMMIT();
    for (int idx = t*16; idx < 16384; idx += 512*16)
        cpa16(smb + O_NW2*4 + idx, (const char*)nw2 + idx);
    if (t < 16) cpa16(smb + O_NB2*4 + t*16, (const char*)nb2 + t*16);
    CPA_COMMIT();

    if (t < 256) {
        int kk = t & 63, node = t >> 6;
        #pragma unroll
        for (int q = 0; q < 4; q++) {
            int u = kk + q*64;
            sm[O_CNT  + u*4 + node]      = g_combnorm[(bi*4 + node)*CC + u];
            sm[O_NACT + (64+u)*4 + node] = g_hagg[(bi*4 + node)*CC + u];
        }
        sm[O_NACT + kk*4 + node] = h[(bi*4 + node)*FF + kk];
    }

    CPA_WAIT(3);
    __syncthreads();

    // post1
    {
        float a0=0,a1=0,a2=0,a3=0;
        #pragma unroll 8
        for (int uu = 0; uu < 32; uu++) {
            int u = r*32 + uu;
            float w = sm[O_PW1 + u*HH + k];
            float4 a4 = *(float4*)&sm[O_CNT + u*4];
            a0 += a4.x*w; a1 += a4.y*w; a2 += a4.z*w; a3 += a4.w*w;
        }
        sm[O_SBUF+(r*4+0)*64+k]=a0; sm[O_SBUF+(r*4+1)*64+k]=a1;
        sm[O_SBUF+(r*4+2)*64+k]=a2; sm[O_SBUF+(r*4+3)*64+k]=a3;
    }
    CPA_WAIT(2);
    __syncthreads();
    if (t < 256) {
        int kk = t & 63, node = t >> 6;
        float s = sm[O_PB1+kk];
        #pragma unroll
        for (int q = 0; q < 8; q++) s += sm[O_SBUF+(q*4+node)*64+kk];
        sm[O_HID + kk*4+node] = silu_f(s);
    }
    __syncthreads();

    // post2
    {
        float a0=0,a1=0,a2=0,a3=0;
        #pragma unroll
        for (int uu = 0; uu < 8; uu++) {
            int u = r*8 + uu;
            float w = sm[O_PW2 + u*HH + k];
            float4 a4 = *(float4*)&sm[O_HID + u*4];
            a0 += a4.x*w; a1 += a4.y*w; a2 += a4.z*w; a3 += a4.w*w;
        }
        sm[O_SBUF+(r*4+0)*64+k]=a0; sm[O_SBUF+(r*4+1)*64+k]=a1;
        sm[O_SBUF+(r*4+2)*64+k]=a2; sm[O_SBUF+(r*4+3)*64+k]=a3;
    }
    CPA_WAIT(1);
    __syncthreads();
    if (t < 256) {
        int kk = t & 63, node = t >> 6;
        float s = sm[O_PB2+kk];
        #pragma unroll
        for (int q = 0; q < 8; q++) s += sm[O_SBUF+(q*4+node)*64+kk];
        sm[O_NACT + (320+kk)*4+node] = silu_f(s);
    }
    __syncthreads();

    // node1
    {
        float a0=0,a1=0,a2=0,a3=0;
        #pragma unroll 8
        for (int uu = 0; uu < 48; uu++) {
            int u = r*48 + uu;
            float w = sm[O_NW1 + u*HH + k];
            float4 a4 = *(float4*)&sm[O_NACT + u*4];
            a0 += a4.x*w; a1 += a4.y*w; a2 += a4.z*w; a3 += a4.w*w;
        }
        sm[O_SBUF+(r*4+0)*64+k]=a0; sm[O_SBUF+(r*4+1)*64+k]=a1;
        sm[O_SBUF+(r*4+2)*64+k]=a2; sm[O_SBUF+(r*4+3)*64+k]=a3;
    }
    CPA_WAIT(0);
    __syncthreads();
    if (t < 256) {
        int kk = t & 63, node = t >> 6;
        float s = sm[O_NB1+kk];
        #pragma unroll
        for (int q = 0; q < 8; q++) s += sm[O_SBUF+(q*4+node)*64+kk];
        sm[O_HID + kk*4+node] = silu_f(s);
    }
    __syncthreads();

    // node2 + residual
    {
        float a0=0,a1=0,a2=0,a3=0;
        #pragma unroll
        for (int uu = 0; uu < 8; uu++) {
            int u = r*8 + uu;
            float w = sm[O_NW2 + u*HH + k];
            float4 a4 = *(float4*)&sm[O_HID + u*4];
            a0 += a4.x*w; a1 += a4.y*w; a2 += a4.z*w; a3 += a4.w*w;
        }
        sm[O_SBUF+(r*4+0)*64+k]=a0; sm[O_SBUF+(r*4+1)*64+k]=a1;
        sm[O_SBUF+(r*4+2)*64+k]=a2; sm[O_SBUF+(r*4+3)*64+k]=a3;
    }
    __syncthreads();
    if (t < 256) {
        int kk = t & 63, node = t >> 6;
        float s = sm[O_NB2+kk];
        #pragma unroll
        for (int q = 0; q < 8; q++) s += sm[O_SBUF+(q*4+node)*64+kk];
        float hn = sm[O_NACT + kk*4+node] + silu_f(s);
        sm[O_HNEW + kk*4+node] = hn;
        out[(bi*4+node)*FF + kk] = hn;
    }
    __syncthreads();

    // vel
    {
        float a0=0,a1=0,a2=0,a3=0;
        #pragma unroll
        for (int uu = 0; uu < 8; uu++) {
            int u = r*8 + uu;
            float w = __ldg(&vw1[u*HH + k]);
            float4 a4 = *(float4*)&sm[O_HNEW + u*4];
            a0 += a4.x*w; a1 += a4.y*w; a2 += a4.z*w; a3 += a4.w*w;
        }
        sm[O_SBUF+(r*4+0)*64+k]=a0; sm[O_SBUF+(r*4+1)*64+k]=a1;
        sm[O_SBUF+(r*4+2)*64+k]=a2; sm[O_SBUF+(r*4+3)*64+k]=a3;
    }
    __syncthreads();
    if (t < 256) {
        int kk = t & 63, node = t >> 6;
        float s = 0.f;
        #pragma unroll
        for (int q = 0; q < 8; q++) s += sm[O_SBUF+(q*4+node)*64+kk];
        float sv = silu_f(s + __ldg(&vb1[kk])) * __ldg(&vw2[kk]);
        sv = warpsumf(sv);
        if ((t & 31) == 0) sm[O_MISC + 4 + (t >> 5)] = sv;
    }
    __syncthreads();
    if (t < 4) sm[O_MISC + t] = sm[O_MISC+4 + t*2] + sm[O_MISC+4 + t*2+1];
    __syncthreads();
    if (t < 12) {
        int nd = t / 3, d = t % 3;
        int gi = bi*4 + nd;
        float vv = v[gi*3 + d];
        float vn = g_deltav[gi*3 + d] + sm[O_MISC + nd]*vv;
        out[BB*NN*FF + gi*3 + d]            = x[gi*3 + d] + vn;
        out[BB*NN*FF + BB*NN*3 + gi*3 + d]  = vn;
    }
}

// ---------------------------------------------------------------------------
extern "C" void kernel_launch(void* const* d_in, const int* in_sizes, int n_in,
                              void* d_out, int out_size)
{
    const float* h        = (const float*)d_in[0];
    const float* x        = (const float*)d_in[1];
    const float* v        = (const float*)d_in[2];
    const float* edge_w1  = (const float*)d_in[3];
    const float* edge_b1  = (const float*)d_in[4];
    const float* edge_w2  = (const float*)d_in[5];
    const float* edge_b2  = (const float*)d_in[6];
    const float* sem_w    = (const float*)d_in[7];
    const float* sem_b    = (const float*)d_in[8];
    const float* post_w1  = (const float*)d_in[9];
    const float* post_b1  = (const float*)d_in[10];
    const float* post_w2  = (const float*)d_in[11];
    const float* post_b2  = (const float*)d_in[12];
    const float* node_w1  = (const float*)d_in[13];
    const float* node_b1  = (const float*)d_in[14];
    const float* node_w2  = (const float*)d_in[15];
    const float* node_b2  = (const float*)d_in[16];
    const float* vel_w1   = (const float*)d_in[17];
    const float* vel_b1   = (const float*)d_in[18];
    const float* vel_w2   = (const float*)d_in[19];
    const float* vmix_w   = (const float*)d_in[20];
    const float* log_gamma= (const float*)d_in[21];
    float* out = (float*)d_out;

    static int cfg_done = 0;
    if (!cfg_done) {
        cudaFuncSetAttribute(node_kernel,
                             cudaFuncAttributeMaxDynamicSharedMemorySize,
                             NODE_SMEM_FLOATS * (int)sizeof(float));
        cudaFuncSetAttribute(attagg_kernel,
                             cudaFuncAttributeMaxDynamicSharedMemorySize,
                             ATT_SMEM_FLOATS * (int)sizeof(float));
        cfg_done = 1;
    }

    pre_kernel<<<BB*NN/2, 256>>>(h, edge_w1, edge_b1);
    edge_kernel<<<BB*NN*2, 128>>>(x, edge_w1, edge_w2, edge_b2, sem_w, sem_b);
    attagg_kernel<<<BB*NN, 256, ATT_SMEM_FLOATS * sizeof(float)>>>(
                                  x, vmix_w, log_gamma);
    node_kernel<<<BB*NN/4, 512, NODE_SMEM_FLOATS * sizeof(float)>>>(
                                  h, x, v,
                                  post_w1, post_b1, post_w2, post_b2,
                                  node_w1, node_b1, node_w2, node_b2,
                                  vel_w1, vel_b1, vel_w2, out);
}